// round 10
// baseline (speedup 1.0000x reference)
#include <cuda_runtime.h>
#include <cuda_fp16.h>
#include <cstdint>

// PolynomialMoE: N=1048576, DIM=2, HID=64, E=4, hard top-1.
// Output (float32): [ out (N*2) | router_logits (N*4) ]
//
// R10: occupancy push. R9 was latency-bound at 16 warps/SM (regs=120 from
// the 64-reg fp32 acc tile). Halve the per-thread M-tile: TILE=128 tokens
// per 256-thread CTA (8 warps x 16 rows), acc[8][4]=32 regs,
// __launch_bounds__(256,3) -> 3 CTAs/SM = 24 warps. Same total MMA count,
// half the per-warp serial chain, 1.5x the latency-hiding warps.
// Math identical to R9 (all-MMA fp16 pipeline, fp32 accum).

typedef unsigned long long U64;

static constexpr int N_MAX = 1 << 20;
static constexpr int TILE  = 128;

__device__ int d_cnt[4];
__device__ int d_perm[4 * N_MAX];
__device__ uint2 d_w2f[4 * 1024];   // [e][ks(4)][nt(8)][lane(32)]
__device__ uint2 d_w1f[4 * 256];    // [e][nt(8)][lane(32)]
__device__ uint2 d_w3f[4 * 128];    // [e][ks(4)][lane(32)]

// ---------------- helpers ----------------
// pack two floats to f16x2, lo = first arg
__device__ __forceinline__ uint32_t packh2(float lo, float hi) {
    uint32_t r;
    asm("cvt.rn.f16x2.f32 %0, %1, %2;" : "=r"(r) : "f"(hi), "f"(lo));
    return r;
}
__device__ __forceinline__ void mma_f16(float c[4], uint32_t a0, uint32_t a1,
                                        uint32_t a2, uint32_t a3,
                                        uint32_t b0, uint32_t b1) {
    asm volatile(
        "mma.sync.aligned.m16n8k16.row.col.f32.f16.f16.f32 "
        "{%0,%1,%2,%3}, {%4,%5,%6,%7}, {%8,%9}, {%0,%1,%2,%3};"
        : "+f"(c[0]), "+f"(c[1]), "+f"(c[2]), "+f"(c[3])
        : "r"(a0), "r"(a1), "r"(a2), "r"(a3), "r"(b0), "r"(b1));
}

// ---------------- Kernel 1: router (2 tok/thread) + fused weight prep ----
__global__ __launch_bounds__(256)
void router_kernel(const float* __restrict__ x,
                   const float* __restrict__ rW,
                   const float* __restrict__ rb,
                   const float* __restrict__ w1,
                   const float* __restrict__ b1,
                   const float* __restrict__ w2,
                   const float* __restrict__ w3,
                   float* __restrict__ out, int n)
{
    __shared__ int scnt[4], gbase[4];
    const int tid = threadIdx.x;
    if (tid < 4) scnt[tid] = 0;

    if (blockIdx.x < 4) {
        // blocks 0-3: w2 fragments for expert e
        const int e = blockIdx.x;
        #pragma unroll
        for (int t = tid; t < 1024; t += 256) {
            const int ks = t >> 8, nt = (t >> 5) & 7, lane = t & 31;
            const int k0 = ks * 16 + (lane & 3) * 2;
            const int nn = nt * 8 + (lane >> 2);
            d_w2f[e * 1024 + t] = make_uint2(
                packh2(w2[e * 4096 + k0 * 64 + nn],
                       w2[e * 4096 + (k0 + 1) * 64 + nn]),
                packh2(w2[e * 4096 + (k0 + 8) * 64 + nn],
                       w2[e * 4096 + (k0 + 9) * 64 + nn]));
        }
    } else if (blockIdx.x < 8) {
        // blocks 4-7: w1_ext and w3 fragments for expert e
        const int e = blockIdx.x - 4;
        {   // w1f: [nt][lane]; K rows: 0=w1[d0], 1=w1[d1], 2=b1, 3..15=0
            const int t = tid;           // 256 threads exactly
            const int lane = t & 31, kb = lane & 3;
            const int nn = ((t >> 5) & 7) * 8 + (lane >> 2);
            uint32_t b0 = 0;
            if (kb == 0) b0 = packh2(w1[e * 128 + nn], w1[e * 128 + 64 + nn]);
            else if (kb == 1) b0 = packh2(b1[e * 64 + nn], 0.f);
            d_w1f[e * 256 + t] = make_uint2(b0, 0u);
        }
        if (tid < 128) {  // w3f: [ks][lane]; N=8 padded, cols 0,1 = w3
            const int t = tid;
            const int ks = t >> 5, lane = t & 31;
            const int col = lane >> 2;
            const int k0 = ks * 16 + (lane & 3) * 2;
            uint2 v = make_uint2(0u, 0u);
            if (col < 2) {
                v.x = packh2(w3[e * 128 + k0 * 2 + col],
                             w3[e * 128 + (k0 + 1) * 2 + col]);
                v.y = packh2(w3[e * 128 + (k0 + 8) * 2 + col],
                             w3[e * 128 + (k0 + 9) * 2 + col]);
            }
            d_w3f[e * 128 + t] = v;
        }
    }
    __syncthreads();

    const float rw0 = rW[0], rw1 = rW[1], rw2 = rW[2], rw3 = rW[3];
    const float rw4 = rW[4], rw5 = rW[5], rw6 = rW[6], rw7 = rW[7];
    const float rb0 = rb[0], rb1 = rb[1], rb2 = rb[2], rb3 = rb[3];

    const int base = blockIdx.x * 512;
    const float4 xq = ((const float4*)x)[base / 2 + tid];
    const unsigned lane = tid & 31;

    int bests[2], wbs[2];
    #pragma unroll
    for (int s = 0; s < 2; s++) {
        const int i = base + 2 * tid + s;
        const float x0 = s ? xq.z : xq.x;
        const float x1 = s ? xq.w : xq.y;
        const float l0 = fmaf(x0, rw0, fmaf(x1, rw4, rb0));
        const float l1 = fmaf(x0, rw1, fmaf(x1, rw5, rb1));
        const float l2 = fmaf(x0, rw2, fmaf(x1, rw6, rb2));
        const float l3 = fmaf(x0, rw3, fmaf(x1, rw7, rb3));
        int best = 0; float bl = l0;
        if (l1 > bl) { bl = l1; best = 1; }
        if (l2 > bl) { bl = l2; best = 2; }
        if (l3 > bl) { bl = l3; best = 3; }
        ((float4*)(out + 2 * (size_t)n))[i] = make_float4(l0, l1, l2, l3);

        unsigned m[4];
        #pragma unroll
        for (int e = 0; e < 4; e++)
            m[e] = __ballot_sync(0xffffffffu, best == e);
        const unsigned mym = m[best];
        const int rank   = __popc(mym & ((1u << lane) - 1));
        const int leader = __ffs(mym) - 1;
        int wb = 0;
        if ((int)lane == leader) wb = atomicAdd(&scnt[best], __popc(mym));
        wb = __shfl_sync(0xffffffffu, wb, leader);
        bests[s] = best;
        wbs[s] = wb + rank;
    }
    __syncthreads();
    if (tid < 4) gbase[tid] = atomicAdd(&d_cnt[tid], scnt[tid]);
    __syncthreads();

    #pragma unroll
    for (int s = 0; s < 2; s++)
        d_perm[bests[s] * N_MAX + gbase[bests[s]] + wbs[s]] = base + 2 * tid + s;
}

// ---------------- Kernel 2: expert tile (all-MMA, 16 rows/warp) -----------
__global__ __launch_bounds__(256, 3)
void expert_kernel(const float* __restrict__ x,
                   const float* __restrict__ b2,
                   const float* __restrict__ b3,
                   float* __restrict__ out)
{
    __shared__ uint2  sW2f[1024];
    __shared__ uint2  sW1f[256];
    __shared__ uint2  sW3f[128];
    __shared__ float2 sX[128];
    __shared__ float  sB2[64];
    __shared__ float  sB3[2];
    __shared__ int    sIdx[128];

    // --- map blockIdx -> (expert, tile) ---
    const int c0 = d_cnt[0], c1 = d_cnt[1], c2 = d_cnt[2], c3 = d_cnt[3];
    const int t0 = (c0 + TILE - 1) / TILE, t1 = (c1 + TILE - 1) / TILE;
    const int t2 = (c2 + TILE - 1) / TILE, t3 = (c3 + TILE - 1) / TILE;
    int b = blockIdx.x, e, lo, cnt;
    if (b < t0)              { e = 0; lo = b; cnt = c0; }
    else if ((b -= t0) < t1) { e = 1; lo = b; cnt = c1; }
    else if ((b -= t1) < t2) { e = 2; lo = b; cnt = c2; }
    else if ((b -= t2) < t3) { e = 3; lo = b; cnt = c3; }
    else return;

    const int tid = threadIdx.x;
    const int tstart = lo * TILE;
    int mvalid = cnt - tstart;
    if (mvalid > TILE) mvalid = TILE;

    // --- stage ---
    {
        const uint4* g2 = (const uint4*)(d_w2f + e * 1024);
        #pragma unroll
        for (int t = tid; t < 512; t += 256) ((uint4*)sW2f)[t] = g2[t];
        if (tid < 128) ((uint4*)sW1f)[tid] = ((const uint4*)(d_w1f + e * 256))[tid];
        else if (tid < 192) ((uint4*)sW3f)[tid - 128] = ((const uint4*)(d_w3f + e * 128))[tid - 128];
        else {
            const int i = tid - 192;
            sB2[i] = b2[e * 64 + i];
        }
        if (tid < 2) sB3[tid] = b3[e * 2 + tid];
        if (tid < TILE) {
            const int token = d_perm[e * N_MAX + tstart + (tid < mvalid ? tid : 0)];
            sIdx[tid] = token;
            sX[tid] = ((const float2*)x)[token];
        }
    }
    __syncthreads();

    const int lane = tid & 31, wid = tid >> 5;
    const int qr = lane >> 2;
    const int kb = lane & 3;
    const int rbase = wid * 16 + qr;      // 8 warps x 16 rows
    const int jb = kb * 2;

    // --- X_ext A-fragments: cols 0,1 = x0,x1 (kb==0); col 2 = 1 (kb==1) ---
    uint32_t xa0 = 0u, xa1 = 0u;          // row p=0 / p=+8; a2,a3 = 0
    {
        const float2 v0 = sX[rbase];
        const float2 v1 = sX[rbase + 8];
        if (kb == 0)      { xa0 = packh2(v0.x, v0.y); xa1 = packh2(v1.x, v1.y); }
        else if (kb == 1) { xa0 = 0x00003C00u;        xa1 = 0x00003C00u; }
    }

    // --- L2 acc init = b2 ---
    float acc[8][4];
    #pragma unroll
    for (int nt = 0; nt < 8; nt++) {
        const float bj0 = sB2[nt * 8 + jb], bj1 = sB2[nt * 8 + jb + 1];
        acc[nt][0] = bj0; acc[nt][1] = bj1;
        acc[nt][2] = bj0; acc[nt][3] = bj1;
    }

    #pragma unroll
    for (int ks = 0; ks < 4; ks++) {
        // L1: h for cols [16ks, 16ks+16) = N-tiles 2ks, 2ks+1
        float l1a[4] = {0.f, 0.f, 0.f, 0.f};
        float l1b[4] = {0.f, 0.f, 0.f, 0.f};
        {
            const uint2 Bw1a = sW1f[(2 * ks) * 32 + lane];
            const uint2 Bw1b = sW1f[(2 * ks + 1) * 32 + lane];
            mma_f16(l1a, xa0, xa1, 0u, 0u, Bw1a.x, Bw1a.y);
            mma_f16(l1b, xa0, xa1, 0u, 0u, Bw1b.x, Bw1b.y);
        }

        // repack D-frag -> A-frag (relu)
        const uint32_t A0 = packh2(fmaxf(l1a[0], 0.f), fmaxf(l1a[1], 0.f));
        const uint32_t A1 = packh2(fmaxf(l1a[2], 0.f), fmaxf(l1a[3], 0.f));
        const uint32_t A2 = packh2(fmaxf(l1b[0], 0.f), fmaxf(l1b[1], 0.f));
        const uint32_t A3 = packh2(fmaxf(l1b[2], 0.f), fmaxf(l1b[3], 0.f));

        // L2
        #pragma unroll
        for (int nt = 0; nt < 8; nt++) {
            const uint2 B = sW2f[(ks * 8 + nt) * 32 + lane];
            mma_f16(acc[nt], A0, A1, A2, A3, B.x, B.y);
        }
    }

    // --- L3 as MMA: relu(acc) @ w3 (N=8 padded; cols 0,1 real) ---
    float o[4] = {0.f, 0.f, 0.f, 0.f};
    #pragma unroll
    for (int ks = 0; ks < 4; ks++) {
        const uint2 Bw3 = sW3f[ks * 32 + lane];
        const uint32_t a0 = packh2(fmaxf(acc[2 * ks][0], 0.f),
                                   fmaxf(acc[2 * ks][1], 0.f));
        const uint32_t a1 = packh2(fmaxf(acc[2 * ks][2], 0.f),
                                   fmaxf(acc[2 * ks][3], 0.f));
        const uint32_t a2 = packh2(fmaxf(acc[2 * ks + 1][0], 0.f),
                                   fmaxf(acc[2 * ks + 1][1], 0.f));
        const uint32_t a3 = packh2(fmaxf(acc[2 * ks + 1][2], 0.f),
                                   fmaxf(acc[2 * ks + 1][3], 0.f));
        mma_f16(o, a0, a1, a2, a3, Bw3.x, Bw3.y);
    }

    if (kb == 0) {   // these lanes hold output cols 0,1
        const float b30 = sB3[0], b31 = sB3[1];
        if (rbase < mvalid)
            ((float2*)out)[sIdx[rbase]] = make_float2(o[0] + b30, o[1] + b31);
        const int r1 = rbase + 8;
        if (r1 < mvalid)
            ((float2*)out)[sIdx[r1]] = make_float2(o[2] + b30, o[3] + b31);
    }
}

extern "C" void kernel_launch(void* const* d_in, const int* in_sizes, int n_in,
                              void* d_out, int out_size)
{
    const float* x  = (const float*)d_in[0];
    const float* rW = (const float*)d_in[1];
    const float* rb = (const float*)d_in[2];
    const float* w1 = (const float*)d_in[3];
    const float* b1 = (const float*)d_in[4];
    const float* w2 = (const float*)d_in[5];
    const float* b2 = (const float*)d_in[6];
    const float* w3 = (const float*)d_in[7];
    const float* b3 = (const float*)d_in[8];
    float* out = (float*)d_out;

    const int n_tok = in_sizes[0] / 2;

    void* cnt_addr = nullptr;
    cudaGetSymbolAddress(&cnt_addr, d_cnt);
    cudaMemsetAsync(cnt_addr, 0, 4 * sizeof(int));

    router_kernel<<<n_tok / 512, 256>>>(x, rW, rb, w1, b1, w2, w3, out, n_tok);

    const int max_tiles = n_tok / TILE + 3;   // per-expert ceil slack
    expert_kernel<<<max_tiles, 256>>>(x, b2, b3, out);
}

// round 11
// speedup vs baseline: 1.1704x; 1.1704x over previous
#include <cuda_runtime.h>
#include <cuda_fp16.h>
#include <cstdint>

// PolynomialMoE: N=1048576, DIM=2, HID=64, E=4, hard top-1.
// Output (float32): [ out (N*2) | router_logits (N*4) ]
//
// R11: R9 shape (TILE=256, 2 row-tiles/thread — best weight-reuse balance;
// R10 proved smaller tiles lose more to L1 traffic than they gain in occ),
// with the non-MMA stream cut:
//  - L1 runs with f16 accumulators: its packed D-fragment IS the L2
//    A-fragment (ntl pairing) -> repack = 4x max.f16x2 (relu) per ks,
//    replacing 16 fmaxf + 8 cvt packs.
//  - L3 A-build: pack-then-relu2 (2 inst/reg vs 3).
//  - w1 B-frag reg1 == 0 -> stored as uint32, LDS.32 + literal 0u.

typedef unsigned long long U64;

static constexpr int N_MAX = 1 << 20;
static constexpr int TILE  = 256;

__device__ int d_cnt[4];
__device__ int d_perm[4 * N_MAX];
__device__ uint2    d_w2f[4 * 1024];  // [e][ks(4)][nt(8)][lane(32)]
__device__ uint32_t d_w1f[4 * 256];   // [e][nt(8)][lane(32)] (reg0 only)
__device__ uint2    d_w3f[4 * 128];   // [e][ks(4)][lane(32)]

// ---------------- helpers ----------------
// pack two floats to f16x2, lo = first arg
__device__ __forceinline__ uint32_t packh2(float lo, float hi) {
    uint32_t r;
    asm("cvt.rn.f16x2.f32 %0, %1, %2;" : "=r"(r) : "f"(hi), "f"(lo));
    return r;
}
// relu on packed f16x2 (max with +0,+0)
__device__ __forceinline__ uint32_t relu2(uint32_t v) {
    uint32_t r;
    asm("max.f16x2 %0, %1, %2;" : "=r"(r) : "r"(v), "r"(0u));
    return r;
}
__device__ __forceinline__ void mma_f16(float c[4], uint32_t a0, uint32_t a1,
                                        uint32_t a2, uint32_t a3,
                                        uint32_t b0, uint32_t b1) {
    asm volatile(
        "mma.sync.aligned.m16n8k16.row.col.f32.f16.f16.f32 "
        "{%0,%1,%2,%3}, {%4,%5,%6,%7}, {%8,%9}, {%0,%1,%2,%3};"
        : "+f"(c[0]), "+f"(c[1]), "+f"(c[2]), "+f"(c[3])
        : "r"(a0), "r"(a1), "r"(a2), "r"(a3), "r"(b0), "r"(b1));
}
// f16-accumulator variant: D,C are 2 packed regs
__device__ __forceinline__ void mma_f16acc(uint32_t c[2], uint32_t a0,
                                           uint32_t a1, uint32_t b0) {
    asm volatile(
        "mma.sync.aligned.m16n8k16.row.col.f16.f16.f16.f16 "
        "{%0,%1}, {%2,%3,%4,%5}, {%6,%7}, {%0,%1};"
        : "+r"(c[0]), "+r"(c[1])
        : "r"(a0), "r"(a1), "r"(0u), "r"(0u), "r"(b0), "r"(0u));
}

// ---------------- Kernel 1: router (2 tok/thread) + fused weight prep ----
__global__ __launch_bounds__(256)
void router_kernel(const float* __restrict__ x,
                   const float* __restrict__ rW,
                   const float* __restrict__ rb,
                   const float* __restrict__ w1,
                   const float* __restrict__ b1,
                   const float* __restrict__ w2,
                   const float* __restrict__ w3,
                   float* __restrict__ out, int n)
{
    __shared__ int scnt[4], gbase[4];
    const int tid = threadIdx.x;
    if (tid < 4) scnt[tid] = 0;

    if (blockIdx.x < 4) {
        // blocks 0-3: w2 fragments for expert e
        const int e = blockIdx.x;
        #pragma unroll
        for (int t = tid; t < 1024; t += 256) {
            const int ks = t >> 8, nt = (t >> 5) & 7, lane = t & 31;
            const int k0 = ks * 16 + (lane & 3) * 2;
            const int nn = nt * 8 + (lane >> 2);
            d_w2f[e * 1024 + t] = make_uint2(
                packh2(w2[e * 4096 + k0 * 64 + nn],
                       w2[e * 4096 + (k0 + 1) * 64 + nn]),
                packh2(w2[e * 4096 + (k0 + 8) * 64 + nn],
                       w2[e * 4096 + (k0 + 9) * 64 + nn]));
        }
    } else if (blockIdx.x < 8) {
        // blocks 4-7: w1_ext and w3 fragments for expert e
        const int e = blockIdx.x - 4;
        {   // w1f: [nt][lane]; K rows: 0=w1[d0], 1=w1[d1], 2=b1, 3..15=0
            const int t = tid;           // 256 threads exactly
            const int lane = t & 31, kb = lane & 3;
            const int nn = ((t >> 5) & 7) * 8 + (lane >> 2);
            uint32_t b0 = 0;
            if (kb == 0) b0 = packh2(w1[e * 128 + nn], w1[e * 128 + 64 + nn]);
            else if (kb == 1) b0 = packh2(b1[e * 64 + nn], 0.f);
            d_w1f[e * 256 + t] = b0;
        }
        if (tid < 128) {  // w3f: [ks][lane]; N=8 padded, cols 0,1 = w3
            const int t = tid;
            const int ks = t >> 5, lane = t & 31;
            const int col = lane >> 2;
            const int k0 = ks * 16 + (lane & 3) * 2;
            uint2 v = make_uint2(0u, 0u);
            if (col < 2) {
                v.x = packh2(w3[e * 128 + k0 * 2 + col],
                             w3[e * 128 + (k0 + 1) * 2 + col]);
                v.y = packh2(w3[e * 128 + (k0 + 8) * 2 + col],
                             w3[e * 128 + (k0 + 9) * 2 + col]);
            }
            d_w3f[e * 128 + t] = v;
        }
    }
    __syncthreads();

    const float rw0 = rW[0], rw1 = rW[1], rw2 = rW[2], rw3 = rW[3];
    const float rw4 = rW[4], rw5 = rW[5], rw6 = rW[6], rw7 = rW[7];
    const float rb0 = rb[0], rb1 = rb[1], rb2 = rb[2], rb3 = rb[3];

    const int base = blockIdx.x * 512;
    const float4 xq = ((const float4*)x)[base / 2 + tid];
    const unsigned lane = tid & 31;

    int bests[2], wbs[2];
    #pragma unroll
    for (int s = 0; s < 2; s++) {
        const int i = base + 2 * tid + s;
        const float x0 = s ? xq.z : xq.x;
        const float x1 = s ? xq.w : xq.y;
        const float l0 = fmaf(x0, rw0, fmaf(x1, rw4, rb0));
        const float l1 = fmaf(x0, rw1, fmaf(x1, rw5, rb1));
        const float l2 = fmaf(x0, rw2, fmaf(x1, rw6, rb2));
        const float l3 = fmaf(x0, rw3, fmaf(x1, rw7, rb3));
        int best = 0; float bl = l0;
        if (l1 > bl) { bl = l1; best = 1; }
        if (l2 > bl) { bl = l2; best = 2; }
        if (l3 > bl) { bl = l3; best = 3; }
        ((float4*)(out + 2 * (size_t)n))[i] = make_float4(l0, l1, l2, l3);

        unsigned m[4];
        #pragma unroll
        for (int e = 0; e < 4; e++)
            m[e] = __ballot_sync(0xffffffffu, best == e);
        const unsigned mym = m[best];
        const int rank   = __popc(mym & ((1u << lane) - 1));
        const int leader = __ffs(mym) - 1;
        int wb = 0;
        if ((int)lane == leader) wb = atomicAdd(&scnt[best], __popc(mym));
        wb = __shfl_sync(0xffffffffu, wb, leader);
        bests[s] = best;
        wbs[s] = wb + rank;
    }
    __syncthreads();
    if (tid < 4) gbase[tid] = atomicAdd(&d_cnt[tid], scnt[tid]);
    __syncthreads();

    #pragma unroll
    for (int s = 0; s < 2; s++)
        d_perm[bests[s] * N_MAX + gbase[bests[s]] + wbs[s]] = base + 2 * tid + s;
}

// ---------------- Kernel 2: expert tile (all-MMA, f16-acc L1) -------------
__global__ __launch_bounds__(256, 2)
void expert_kernel(const float* __restrict__ x,
                   const float* __restrict__ b2,
                   const float* __restrict__ b3,
                   float* __restrict__ out)
{
    __shared__ uint2    sW2f[1024];
    __shared__ uint32_t sW1f[256];
    __shared__ uint2    sW3f[128];
    __shared__ float2   sX[256];
    __shared__ float    sB2[64];
    __shared__ float    sB3[2];
    __shared__ int      sIdx[256];

    // --- map blockIdx -> (expert, tile) ---
    const int c0 = d_cnt[0], c1 = d_cnt[1], c2 = d_cnt[2], c3 = d_cnt[3];
    const int t0 = (c0 + TILE - 1) / TILE, t1 = (c1 + TILE - 1) / TILE;
    const int t2 = (c2 + TILE - 1) / TILE, t3 = (c3 + TILE - 1) / TILE;
    int b = blockIdx.x, e, lo, cnt;
    if (b < t0)              { e = 0; lo = b; cnt = c0; }
    else if ((b -= t0) < t1) { e = 1; lo = b; cnt = c1; }
    else if ((b -= t1) < t2) { e = 2; lo = b; cnt = c2; }
    else if ((b -= t2) < t3) { e = 3; lo = b; cnt = c3; }
    else return;

    const int tid = threadIdx.x;
    const int tstart = lo * TILE;
    int mvalid = cnt - tstart;
    if (mvalid > TILE) mvalid = TILE;

    // --- stage ---
    {
        const uint4* g2 = (const uint4*)(d_w2f + e * 1024);
        #pragma unroll
        for (int t = tid; t < 512; t += 256) ((uint4*)sW2f)[t] = g2[t];
        if (tid < 64) ((uint4*)sW1f)[tid] = ((const uint4*)(d_w1f + e * 256))[tid];
        else if (tid < 128) ((uint4*)sW3f)[tid - 64] = ((const uint4*)(d_w3f + e * 128))[tid - 64];
        else if (tid < 192) {
            const int i = tid - 128;
            sB2[i] = b2[e * 64 + i];
        }
        if (tid < 2) sB3[tid] = b3[e * 2 + tid];
        const int token = d_perm[e * N_MAX + tstart + (tid < mvalid ? tid : 0)];
        sIdx[tid] = token;
        sX[tid] = ((const float2*)x)[token];
    }
    __syncthreads();

    const int lane = tid & 31, wid = tid >> 5;
    const int qr = lane >> 2;
    const int kb = lane & 3;
    const int rbase = wid * 32 + qr;
    const int jb = kb * 2;

    // --- X_ext A-fragments: cols 0,1 = x0,x1 (kb==0); col 2 = 1 (kb==1) ---
    uint32_t xa[2][2];                    // [mt][row p]; a2,a3 = 0
    #pragma unroll
    for (int mt = 0; mt < 2; mt++) {
        const float2 v0 = sX[rbase + mt * 16];
        const float2 v1 = sX[rbase + mt * 16 + 8];
        uint32_t p0 = 0u, p1 = 0u;
        if (kb == 0)      { p0 = packh2(v0.x, v0.y); p1 = packh2(v1.x, v1.y); }
        else if (kb == 1) { p0 = 0x00003C00u;        p1 = 0x00003C00u; }
        xa[mt][0] = p0; xa[mt][1] = p1;
    }

    // --- L2 acc init = b2 ---
    float acc[2][8][4];
    #pragma unroll
    for (int nt = 0; nt < 8; nt++) {
        const float bj0 = sB2[nt * 8 + jb], bj1 = sB2[nt * 8 + jb + 1];
        #pragma unroll
        for (int mt = 0; mt < 2; mt++) {
            acc[mt][nt][0] = bj0; acc[mt][nt][1] = bj1;
            acc[mt][nt][2] = bj0; acc[mt][nt][3] = bj1;
        }
    }

    #pragma unroll
    for (int ks = 0; ks < 4; ks++) {
        // L1 (f16 acc): D-frag {reg0,reg1} of ntl is already the A-frag
        // pair {a(2ntl), a(2ntl+1)} for L2's K-tile ks. relu via max.f16x2.
        const uint32_t Bw1a = sW1f[(2 * ks) * 32 + lane];
        const uint32_t Bw1b = sW1f[(2 * ks + 1) * 32 + lane];
        uint32_t A2[2][4];
        #pragma unroll
        for (int mt = 0; mt < 2; mt++) {
            uint32_t da[2] = {0u, 0u}, db[2] = {0u, 0u};
            mma_f16acc(da, xa[mt][0], xa[mt][1], Bw1a);
            mma_f16acc(db, xa[mt][0], xa[mt][1], Bw1b);
            A2[mt][0] = relu2(da[0]);
            A2[mt][1] = relu2(da[1]);
            A2[mt][2] = relu2(db[0]);
            A2[mt][3] = relu2(db[1]);
        }

        // L2
        #pragma unroll
        for (int nt = 0; nt < 8; nt++) {
            const uint2 B = sW2f[(ks * 8 + nt) * 32 + lane];
            mma_f16(acc[0][nt], A2[0][0], A2[0][1], A2[0][2], A2[0][3], B.x, B.y);
            mma_f16(acc[1][nt], A2[1][0], A2[1][1], A2[1][2], A2[1][3], B.x, B.y);
        }
    }

    // --- L3 as MMA: relu(acc) @ w3 (N=8 padded; cols 0,1 real) ---
    float o[2][4];
    #pragma unroll
    for (int mt = 0; mt < 2; mt++)
        #pragma unroll
        for (int q = 0; q < 4; q++) o[mt][q] = 0.f;

    #pragma unroll
    for (int ks = 0; ks < 4; ks++) {
        const uint2 Bw3 = sW3f[ks * 32 + lane];
        #pragma unroll
        for (int mt = 0; mt < 2; mt++) {
            const uint32_t a0 = relu2(packh2(acc[mt][2 * ks][0],
                                             acc[mt][2 * ks][1]));
            const uint32_t a1 = relu2(packh2(acc[mt][2 * ks][2],
                                             acc[mt][2 * ks][3]));
            const uint32_t a2 = relu2(packh2(acc[mt][2 * ks + 1][0],
                                             acc[mt][2 * ks + 1][1]));
            const uint32_t a3 = relu2(packh2(acc[mt][2 * ks + 1][2],
                                             acc[mt][2 * ks + 1][3]));
            mma_f16(o[mt], a0, a1, a2, a3, Bw3.x, Bw3.y);
        }
    }

    if (kb == 0) {   // these lanes hold output cols 0,1
        const float b30 = sB3[0], b31 = sB3[1];
        #pragma unroll
        for (int mt = 0; mt < 2; mt++) {
            const int r0 = rbase + mt * 16;
            if (r0 < mvalid)
                ((float2*)out)[sIdx[r0]] = make_float2(o[mt][0] + b30,
                                                       o[mt][1] + b31);
            const int r1 = r0 + 8;
            if (r1 < mvalid)
                ((float2*)out)[sIdx[r1]] = make_float2(o[mt][2] + b30,
                                                       o[mt][3] + b31);
        }
    }
}

extern "C" void kernel_launch(void* const* d_in, const int* in_sizes, int n_in,
                              void* d_out, int out_size)
{
    const float* x  = (const float*)d_in[0];
    const float* rW = (const float*)d_in[1];
    const float* rb = (const float*)d_in[2];
    const float* w1 = (const float*)d_in[3];
    const float* b1 = (const float*)d_in[4];
    const float* w2 = (const float*)d_in[5];
    const float* b2 = (const float*)d_in[6];
    const float* w3 = (const float*)d_in[7];
    const float* b3 = (const float*)d_in[8];
    float* out = (float*)d_out;

    const int n_tok = in_sizes[0] / 2;

    void* cnt_addr = nullptr;
    cudaGetSymbolAddress(&cnt_addr, d_cnt);
    cudaMemsetAsync(cnt_addr, 0, 4 * sizeof(int));

    router_kernel<<<n_tok / 512, 256>>>(x, rW, rb, w1, b1, w2, w3, out, n_tok);

    const int max_tiles = n_tok / TILE + 3;   // per-expert ceil slack
    expert_kernel<<<max_tiles, 256>>>(x, b2, b3, out);
}